// round 6
// baseline (speedup 1.0000x reference)
#include <cuda_runtime.h>
#include <cstdint>

#define DINL __device__ __forceinline__

namespace {
constexpr int SEQ = 2048, DH = 64, BQ = 128, BK = 64, NTILE = SEQ / BK;
constexpr int NTHR = 128;                  // 4 warps x 32 q-rows each
constexpr int RSTRIDE = 36;                // u32 words per row (144 B)
constexpr int PART = 64 * RSTRIDE;         // words per operand part
constexpr int PKH = 0, PKL = PART, PVH = 2 * PART, PVL = 3 * PART;
constexpr int BUFW = 4 * PART;             // 9216 words per tile buffer
constexpr uint32_t SMEM_BYTES = 2u * BUFW * 4u;   // 73728 B (double buffered)
}  // namespace

DINL uint32_t pkbf(float lo, float hi) {   // word = {lo16: bf(lo), hi16: bf(hi)}
    uint32_t r;
    asm("cvt.rn.bf16x2.f32 %0, %1, %2;" : "=r"(r) : "f"(hi), "f"(lo));
    return r;
}
DINL float lof(uint32_t w) { return __uint_as_float(w << 16); }
DINL float hif(uint32_t w) { return __uint_as_float(w & 0xffff0000u); }

DINL void split_store(uint32_t* hp, uint32_t* lp, float x, float y) {
    uint32_t h = pkbf(x, y);
    *hp = h;
    *lp = pkbf(x - lof(h), y - hif(h));
}

DINL void mma16816(float* cc, const uint32_t* a, uint32_t b0, uint32_t b1) {
    asm volatile(
        "mma.sync.aligned.m16n8k16.row.col.f32.bf16.bf16.f32 "
        "{%0,%1,%2,%3}, {%4,%5,%6,%7}, {%8,%9}, {%0,%1,%2,%3};"
        : "+f"(cc[0]), "+f"(cc[1]), "+f"(cc[2]), "+f"(cc[3])
        : "r"(a[0]), "r"(a[1]), "r"(a[2]), "r"(a[3]), "r"(b0), "r"(b1));
}

// Convert one K/V tile (64 keys x 64 d fp32) to hi/lo bf16 smem parts.
// K kept [key][d] (pairs in d); V transposed to [d][key] (pairs in key).
DINL void fill_tile(uint32_t* buf, const float* Kt, const float* Vt, int tid) {
    {
        const int key = tid >> 1, dq = (tid & 1) * 32;
        const float4* kp = (const float4*)(Kt + key * DH + dq);
        uint32_t* kh = buf + PKH + key * RSTRIDE + (dq >> 1);
        uint32_t* kl = buf + PKL + key * RSTRIDE + (dq >> 1);
        #pragma unroll
        for (int j = 0; j < 8; ++j) {
            float4 v = kp[j];
            split_store(kh + 2 * j, kl + 2 * j, v.x, v.y);
            split_store(kh + 2 * j + 1, kl + 2 * j + 1, v.z, v.w);
        }
    }
    {
        const int p = tid & 31, d0 = (tid >> 5) * 16;
        const float4* va = (const float4*)(Vt + (2 * p) * DH + d0);
        const float4* vb = (const float4*)(Vt + (2 * p + 1) * DH + d0);
        #pragma unroll
        for (int j = 0; j < 4; ++j) {
            float4 a = va[j], b = vb[j];
            float af[4] = {a.x, a.y, a.z, a.w};
            float bf4[4] = {b.x, b.y, b.z, b.w};
            #pragma unroll
            for (int e = 0; e < 4; ++e) {
                int d = d0 + 4 * j + e;
                split_store(buf + PVH + d * RSTRIDE + p,
                            buf + PVL + d * RSTRIDE + p, af[e], bf4[e]);
            }
        }
    }
}

__global__ void __launch_bounds__(NTHR, 2)
fa_mma_kernel(const float* __restrict__ Q, const float* __restrict__ K,
              const float* __restrict__ V, const int* __restrict__ M,
              float* __restrict__ O) {
    extern __shared__ uint32_t sm[];
    const int tid = threadIdx.x;
    const int w = tid >> 5, lane = tid & 31;
    const int g = lane >> 2, c = lane & 3;
    const int q0 = blockIdx.x * BQ, bh = blockIdx.y;

    const float* Qg = Q + ((size_t)bh * SEQ + q0) * DH;
    const float* Kg = K + (size_t)bh * SEQ * DH;
    const float* Vg = V + (size_t)bh * SEQ * DH;

    int rr[2][2];
    rr[0][0] = w * 32 + g;      rr[0][1] = rr[0][0] + 8;
    rr[1][0] = rr[0][0] + 16;   rr[1][1] = rr[1][0] + 8;
    const int* Mbase = M + ((size_t)bh * SEQ + q0) * SEQ;

    // ---- Q fragments (x 1/8 exact), hi/lo bf16, persistent ----
    uint32_t qh[2][4][4], ql[2][4][4];
    #pragma unroll
    for (int rb = 0; rb < 2; ++rb) {
        #pragma unroll
        for (int s = 0; s < 4; ++s) {
            const int col = 16 * s + 2 * c;
            float2 x0 = *(const float2*)(Qg + rr[rb][0] * DH + col);
            float2 x1 = *(const float2*)(Qg + rr[rb][1] * DH + col);
            float2 x2 = *(const float2*)(Qg + rr[rb][0] * DH + col + 8);
            float2 x3 = *(const float2*)(Qg + rr[rb][1] * DH + col + 8);
            split_store(&qh[rb][s][0], &ql[rb][s][0], x0.x * .125f, x0.y * .125f);
            split_store(&qh[rb][s][1], &ql[rb][s][1], x1.x * .125f, x1.y * .125f);
            split_store(&qh[rb][s][2], &ql[rb][s][2], x2.x * .125f, x2.y * .125f);
            split_store(&qh[rb][s][3], &ql[rb][s][3], x3.x * .125f, x3.y * .125f);
        }
    }

    uint32_t* bufA = sm;
    uint32_t* bufB = sm + BUFW;
    fill_tile(bufA, Kg, Vg, tid);
    __syncthreads();

    float oc[2][8][4] = {};
    float ls[2][2] = {};

    for (int t = 0; t < NTILE; ++t) {
        const uint32_t* Bk = bufA + g * RSTRIDE + c;

        // ---- S = Qhat K^T : 3-pass, pass-major in nt-groups of 4 ----
        float sc[2][8][4] = {};
        #pragma unroll
        for (int s = 0; s < 4; ++s) {
            #pragma unroll
            for (int ng = 0; ng < 2; ++ng) {
                uint32_t bw[4][4];
                #pragma unroll
                for (int j = 0; j < 4; ++j) {
                    const int nt = ng * 4 + j;
                    bw[j][0] = Bk[PKH + nt * 288 + s * 8];
                    bw[j][1] = Bk[PKH + nt * 288 + s * 8 + 4];
                    bw[j][2] = Bk[PKL + nt * 288 + s * 8];
                    bw[j][3] = Bk[PKL + nt * 288 + s * 8 + 4];
                }
                #pragma unroll
                for (int j = 0; j < 4; ++j) {
                    const int nt = ng * 4 + j;
                    mma16816(sc[0][nt], qh[0][s], bw[j][0], bw[j][1]);
                    mma16816(sc[1][nt], qh[1][s], bw[j][0], bw[j][1]);
                }
                #pragma unroll
                for (int j = 0; j < 4; ++j) {
                    const int nt = ng * 4 + j;
                    mma16816(sc[0][nt], qh[0][s], bw[j][2], bw[j][3]);
                    mma16816(sc[1][nt], qh[1][s], bw[j][2], bw[j][3]);
                }
                #pragma unroll
                for (int j = 0; j < 4; ++j) {
                    const int nt = ng * 4 + j;
                    mma16816(sc[0][nt], ql[0][s], bw[j][0], bw[j][1]);
                    mma16816(sc[1][nt], ql[1][s], bw[j][0], bw[j][1]);
                }
            }
        }

        // prefetch+convert next tile while QK drains on the tensor pipe
        if (t + 1 < NTILE)
            fill_tile(bufB, Kg + (size_t)(t + 1) * BK * DH,
                      Vg + (size_t)(t + 1) * BK * DH, tid);

        // ---- mask bits for this tile (LDG hidden behind fill/QK drain) ----
        uint32_t mbits[2];
        #pragma unroll
        for (int rb = 0; rb < 2; ++rb) {
            const int* M0 = Mbase + (size_t)rr[rb][0] * SEQ + t * BK + 2 * c;
            const int* M1 = Mbase + (size_t)rr[rb][1] * SEQ + t * BK + 2 * c;
            uint32_t bits = 0;
            #pragma unroll
            for (int nt = 0; nt < 8; ++nt) {
                int2 m0 = *(const int2*)(M0 + nt * 8);
                int2 m1 = *(const int2*)(M1 + nt * 8);
                bits |= ((m0.x ? 1u : 0u) | (m0.y ? 2u : 0u) |
                         (m1.x ? 4u : 0u) | (m1.y ? 8u : 0u)) << (nt * 4);
            }
            mbits[rb] = bits;
        }

        // ---- softmax in place: p = mask ? exp(s) : 0 (unshifted) ----
        #pragma unroll
        for (int rb = 0; rb < 2; ++rb) {
            #pragma unroll
            for (int nt = 0; nt < 8; ++nt) {
                const uint32_t b = mbits[rb] >> (nt * 4);
                float e0 = (b & 1u) ? __expf(sc[rb][nt][0]) : 0.f;
                float e1 = (b & 2u) ? __expf(sc[rb][nt][1]) : 0.f;
                float e2 = (b & 4u) ? __expf(sc[rb][nt][2]) : 0.f;
                float e3 = (b & 8u) ? __expf(sc[rb][nt][3]) : 0.f;
                ls[rb][0] += e0 + e1;
                ls[rb][1] += e2 + e3;
                sc[rb][nt][0] = e0; sc[rb][nt][1] = e1;
                sc[rb][nt][2] = e2; sc[rb][nt][3] = e3;
            }
        }

        // ---- O += P V : 3-pass, P fragments built per-s (regs transient) ----
        #pragma unroll
        for (int s = 0; s < 4; ++s) {
            uint32_t pah[2][4], pal[2][4];
            #pragma unroll
            for (int rb = 0; rb < 2; ++rb) {
                split_store(&pah[rb][0], &pal[rb][0], sc[rb][2*s][0], sc[rb][2*s][1]);
                split_store(&pah[rb][1], &pal[rb][1], sc[rb][2*s][2], sc[rb][2*s][3]);
                split_store(&pah[rb][2], &pal[rb][2], sc[rb][2*s+1][0], sc[rb][2*s+1][1]);
                split_store(&pah[rb][3], &pal[rb][3], sc[rb][2*s+1][2], sc[rb][2*s+1][3]);
            }
            #pragma unroll
            for (int ng = 0; ng < 2; ++ng) {
                uint32_t vw[4][4];
                #pragma unroll
                for (int j = 0; j < 4; ++j) {
                    const int nt = ng * 4 + j;
                    vw[j][0] = Bk[PVH + nt * 288 + s * 8];
                    vw[j][1] = Bk[PVH + nt * 288 + s * 8 + 4];
                    vw[j][2] = Bk[PVL + nt * 288 + s * 8];
                    vw[j][3] = Bk[PVL + nt * 288 + s * 8 + 4];
                }
                #pragma unroll
                for (int j = 0; j < 4; ++j) {
                    const int nt = ng * 4 + j;
                    mma16816(oc[0][nt], pah[0], vw[j][0], vw[j][1]);
                    mma16816(oc[1][nt], pah[1], vw[j][0], vw[j][1]);
                }
                #pragma unroll
                for (int j = 0; j < 4; ++j) {
                    const int nt = ng * 4 + j;
                    mma16816(oc[0][nt], pah[0], vw[j][2], vw[j][3]);
                    mma16816(oc[1][nt], pah[1], vw[j][2], vw[j][3]);
                }
                #pragma unroll
                for (int j = 0; j < 4; ++j) {
                    const int nt = ng * 4 + j;
                    mma16816(oc[0][nt], pal[0], vw[j][0], vw[j][1]);
                    mma16816(oc[1][nt], pal[1], vw[j][0], vw[j][1]);
                }
            }
        }
        __syncthreads();
        uint32_t* tmp = bufA; bufA = bufB; bufB = tmp;
    }

    // ---- epilogue: reduce l over the quad, scale, store ----
    float* Og = O + ((size_t)bh * SEQ + q0) * DH;
    #pragma unroll
    for (int rb = 0; rb < 2; ++rb) {
        float l0 = ls[rb][0], l1 = ls[rb][1];
        l0 += __shfl_xor_sync(0xffffffffu, l0, 1);
        l0 += __shfl_xor_sync(0xffffffffu, l0, 2);
        l1 += __shfl_xor_sync(0xffffffffu, l1, 1);
        l1 += __shfl_xor_sync(0xffffffffu, l1, 2);
        const float i0 = 1.f / l0, i1 = 1.f / l1;
        #pragma unroll
        for (int nt = 0; nt < 8; ++nt) {
            *(float2*)(Og + rr[rb][0] * DH + nt * 8 + 2 * c) =
                make_float2(oc[rb][nt][0] * i0, oc[rb][nt][1] * i0);
            *(float2*)(Og + rr[rb][1] * DH + nt * 8 + 2 * c) =
                make_float2(oc[rb][nt][2] * i1, oc[rb][nt][3] * i1);
        }
    }
}

extern "C" void kernel_launch(void* const* d_in, const int* in_sizes, int n_in,
                              void* d_out, int out_size) {
    const float* Q = (const float*)d_in[0];
    const float* K = (const float*)d_in[1];
    const float* V = (const float*)d_in[2];
    const int*   M = (const int*)d_in[3];
    float* O = (float*)d_out;
    (void)in_sizes; (void)n_in; (void)out_size;

    cudaFuncSetAttribute(fa_mma_kernel,
                         cudaFuncAttributeMaxDynamicSharedMemorySize,
                         (int)SMEM_BYTES);
    dim3 grid(SEQ / BQ, 32);   // 16 q-tiles x (B*H)
    fa_mma_kernel<<<grid, NTHR, SMEM_BYTES>>>(Q, K, V, M, O);
}

// round 7
// speedup vs baseline: 1.0950x; 1.0950x over previous
#include <cuda_runtime.h>
#include <cstdint>

#define DINL __device__ __forceinline__

namespace {
constexpr int SEQ = 2048, DH = 64, BQ = 128, BK = 64, NTILE = SEQ / BK;
constexpr int NTHR = 128;                  // 4 warps x 32 q-rows each
constexpr int RSTRIDE = 36;                // u32 words per row (144 B)
constexpr int PART = 64 * RSTRIDE;         // words per operand part
constexpr int PKH = 0, PKL = PART, PVH = 2 * PART, PVL = 3 * PART;
constexpr int BUFW = 4 * PART;             // 9216 words per tile buffer
constexpr uint32_t SMEM_BYTES = 2u * BUFW * 4u;   // 73728 B (double buffered)
}  // namespace

DINL uint32_t pkbf(float lo, float hi) {   // word = {lo16: bf(lo), hi16: bf(hi)}
    uint32_t r;
    asm("cvt.rn.bf16x2.f32 %0, %1, %2;" : "=r"(r) : "f"(hi), "f"(lo));
    return r;
}
DINL float lof(uint32_t w) { return __uint_as_float(w << 16); }
DINL float hif(uint32_t w) { return __uint_as_float(w & 0xffff0000u); }

DINL void split_store(uint32_t* hp, uint32_t* lp, float x, float y) {
    uint32_t h = pkbf(x, y);
    *hp = h;
    *lp = pkbf(x - lof(h), y - hif(h));
}

DINL void mma16816(float* cc, const uint32_t* a, uint32_t b0, uint32_t b1) {
    asm volatile(
        "mma.sync.aligned.m16n8k16.row.col.f32.bf16.bf16.f32 "
        "{%0,%1,%2,%3}, {%4,%5,%6,%7}, {%8,%9}, {%0,%1,%2,%3};"
        : "+f"(cc[0]), "+f"(cc[1]), "+f"(cc[2]), "+f"(cc[3])
        : "r"(a[0]), "r"(a[1]), "r"(a[2]), "r"(a[3]), "r"(b0), "r"(b1));
}

// Convert one K/V tile (64 keys x 64 d fp32) to hi/lo bf16 smem parts.
// K kept [key][d] (pairs in d); V transposed to [d][key] (pairs in key).
DINL void fill_tile(uint32_t* buf, const float* Kt, const float* Vt, int tid) {
    {
        const int key = tid >> 1, dq = (tid & 1) * 32;
        const float4* kp = (const float4*)(Kt + key * DH + dq);
        uint32_t* kh = buf + PKH + key * RSTRIDE + (dq >> 1);
        uint32_t* kl = buf + PKL + key * RSTRIDE + (dq >> 1);
        #pragma unroll
        for (int j = 0; j < 8; ++j) {
            float4 v = kp[j];
            split_store(kh + 2 * j, kl + 2 * j, v.x, v.y);
            split_store(kh + 2 * j + 1, kl + 2 * j + 1, v.z, v.w);
        }
    }
    {
        const int p = tid & 31, d0 = (tid >> 5) * 16;
        const float4* va = (const float4*)(Vt + (2 * p) * DH + d0);
        const float4* vb = (const float4*)(Vt + (2 * p + 1) * DH + d0);
        #pragma unroll
        for (int j = 0; j < 4; ++j) {
            float4 a = va[j], b = vb[j];
            float af[4] = {a.x, a.y, a.z, a.w};
            float bf4[4] = {b.x, b.y, b.z, b.w};
            #pragma unroll
            for (int e = 0; e < 4; ++e) {
                int d = d0 + 4 * j + e;
                split_store(buf + PVH + d * RSTRIDE + p,
                            buf + PVL + d * RSTRIDE + p, af[e], bf4[e]);
            }
        }
    }
}

__global__ void __launch_bounds__(NTHR, 2)
fa_mma_kernel(const float* __restrict__ Q, const float* __restrict__ K,
              const float* __restrict__ V, const int* __restrict__ M,
              float* __restrict__ O) {
    extern __shared__ uint32_t sm[];
    const int tid = threadIdx.x;
    const int w = tid >> 5, lane = tid & 31;
    const int g = lane >> 2, c = lane & 3;
    const int q0 = blockIdx.x * BQ, bh = blockIdx.y;

    const float* Qg = Q + ((size_t)bh * SEQ + q0) * DH;
    const float* Kg = K + (size_t)bh * SEQ * DH;
    const float* Vg = V + (size_t)bh * SEQ * DH;

    int rr[2][2];
    rr[0][0] = w * 32 + g;      rr[0][1] = rr[0][0] + 8;
    rr[1][0] = rr[0][0] + 16;   rr[1][1] = rr[1][0] + 8;
    const int* Mbase = M + ((size_t)bh * SEQ + q0) * SEQ;

    // ---- Q fragments (x 1/8 exact), hi/lo bf16, persistent ----
    uint32_t qh[2][4][4], ql[2][4][4];
    #pragma unroll
    for (int rb = 0; rb < 2; ++rb) {
        #pragma unroll
        for (int s = 0; s < 4; ++s) {
            const int col = 16 * s + 2 * c;
            float2 x0 = *(const float2*)(Qg + rr[rb][0] * DH + col);
            float2 x1 = *(const float2*)(Qg + rr[rb][1] * DH + col);
            float2 x2 = *(const float2*)(Qg + rr[rb][0] * DH + col + 8);
            float2 x3 = *(const float2*)(Qg + rr[rb][1] * DH + col + 8);
            split_store(&qh[rb][s][0], &ql[rb][s][0], x0.x * .125f, x0.y * .125f);
            split_store(&qh[rb][s][1], &ql[rb][s][1], x1.x * .125f, x1.y * .125f);
            split_store(&qh[rb][s][2], &ql[rb][s][2], x2.x * .125f, x2.y * .125f);
            split_store(&qh[rb][s][3], &ql[rb][s][3], x3.x * .125f, x3.y * .125f);
        }
    }

    uint32_t* bufA = sm;
    uint32_t* bufB = sm + BUFW;
    fill_tile(bufA, Kg, Vg, tid);
    __syncthreads();

    float oc[2][8][4] = {};
    float ls[2][2] = {};

    for (int t = 0; t < NTILE; ++t) {
        const uint32_t* Bk = bufA + g * RSTRIDE + c;

        #pragma unroll
        for (int hf = 0; hf < 2; ++hf) {
            // ---- mask bits for this half (LDG early; drains under QK) ----
            uint32_t mbits[2];
            #pragma unroll
            for (int rb = 0; rb < 2; ++rb) {
                const int* M0 =
                    Mbase + (size_t)rr[rb][0] * SEQ + t * BK + hf * 32 + 2 * c;
                const int* M1 =
                    Mbase + (size_t)rr[rb][1] * SEQ + t * BK + hf * 32 + 2 * c;
                uint32_t bits = 0;
                #pragma unroll
                for (int j = 0; j < 4; ++j) {
                    int2 m0 = *(const int2*)(M0 + j * 8);
                    int2 m1 = *(const int2*)(M1 + j * 8);
                    bits |= ((m0.x ? 1u : 0u) | (m0.y ? 2u : 0u) |
                             (m1.x ? 4u : 0u) | (m1.y ? 8u : 0u)) << (j * 4);
                }
                mbits[rb] = bits;
            }

            // ---- S(half) = Qhat K^T : 3 passes, 8 indep accumulators ----
            float sc[2][4][4] = {};
            #pragma unroll
            for (int s = 0; s < 4; ++s) {
                uint32_t b0[4], b1[4], l0[4], l1[4];
                #pragma unroll
                for (int j = 0; j < 4; ++j) {
                    const int nt = hf * 4 + j;
                    b0[j] = Bk[PKH + nt * 288 + s * 8];
                    b1[j] = Bk[PKH + nt * 288 + s * 8 + 4];
                    l0[j] = Bk[PKL + nt * 288 + s * 8];
                    l1[j] = Bk[PKL + nt * 288 + s * 8 + 4];
                }
                #pragma unroll
                for (int j = 0; j < 4; ++j) {
                    mma16816(sc[0][j], qh[0][s], b0[j], b1[j]);
                    mma16816(sc[1][j], qh[1][s], b0[j], b1[j]);
                }
                #pragma unroll
                for (int j = 0; j < 4; ++j) {
                    mma16816(sc[0][j], qh[0][s], l0[j], l1[j]);
                    mma16816(sc[1][j], qh[1][s], l0[j], l1[j]);
                }
                #pragma unroll
                for (int j = 0; j < 4; ++j) {
                    mma16816(sc[0][j], ql[0][s], b0[j], b1[j]);
                    mma16816(sc[1][j], ql[1][s], b0[j], b1[j]);
                }
            }

            // ---- softmax in place: p = mask ? exp(s) : 0 (unshifted) ----
            #pragma unroll
            for (int rb = 0; rb < 2; ++rb) {
                #pragma unroll
                for (int j = 0; j < 4; ++j) {
                    const uint32_t b = mbits[rb] >> (j * 4);
                    float e0 = (b & 1u) ? __expf(sc[rb][j][0]) : 0.f;
                    float e1 = (b & 2u) ? __expf(sc[rb][j][1]) : 0.f;
                    float e2 = (b & 4u) ? __expf(sc[rb][j][2]) : 0.f;
                    float e3 = (b & 8u) ? __expf(sc[rb][j][3]) : 0.f;
                    ls[rb][0] += e0 + e1;
                    ls[rb][1] += e2 + e3;
                    sc[rb][j][0] = e0; sc[rb][j][1] = e1;
                    sc[rb][j][2] = e2; sc[rb][j][3] = e3;
                }
            }

            // ---- O += P(half) V(half rows) : 3 passes ----
            #pragma unroll
            for (int sp = 0; sp < 2; ++sp) {
                const int s = hf * 2 + sp;
                uint32_t pah[2][4], pal[2][4];
                #pragma unroll
                for (int rb = 0; rb < 2; ++rb) {
                    split_store(&pah[rb][0], &pal[rb][0],
                                sc[rb][2 * sp][0], sc[rb][2 * sp][1]);
                    split_store(&pah[rb][1], &pal[rb][1],
                                sc[rb][2 * sp][2], sc[rb][2 * sp][3]);
                    split_store(&pah[rb][2], &pal[rb][2],
                                sc[rb][2 * sp + 1][0], sc[rb][2 * sp + 1][1]);
                    split_store(&pah[rb][3], &pal[rb][3],
                                sc[rb][2 * sp + 1][2], sc[rb][2 * sp + 1][3]);
                }
                #pragma unroll
                for (int ng = 0; ng < 2; ++ng) {
                    uint32_t v0[4], v1[4], w0[4], w1[4];
                    #pragma unroll
                    for (int j = 0; j < 4; ++j) {
                        const int nt = ng * 4 + j;
                        v0[j] = Bk[PVH + nt * 288 + s * 8];
                        v1[j] = Bk[PVH + nt * 288 + s * 8 + 4];
                        w0[j] = Bk[PVL + nt * 288 + s * 8];
                        w1[j] = Bk[PVL + nt * 288 + s * 8 + 4];
                    }
                    #pragma unroll
                    for (int j = 0; j < 4; ++j) {
                        mma16816(oc[0][ng * 4 + j], pah[0], v0[j], v1[j]);
                        mma16816(oc[1][ng * 4 + j], pah[1], v0[j], v1[j]);
                    }
                    #pragma unroll
                    for (int j = 0; j < 4; ++j) {
                        mma16816(oc[0][ng * 4 + j], pah[0], w0[j], w1[j]);
                        mma16816(oc[1][ng * 4 + j], pah[1], w0[j], w1[j]);
                    }
                    #pragma unroll
                    for (int j = 0; j < 4; ++j) {
                        mma16816(oc[0][ng * 4 + j], pal[0], v0[j], v1[j]);
                        mma16816(oc[1][ng * 4 + j], pal[1], v0[j], v1[j]);
                    }
                }
            }

            // prefetch+convert next tile between halves (sc is dead here)
            if (hf == 0 && t + 1 < NTILE)
                fill_tile(bufB, Kg + (size_t)(t + 1) * BK * DH,
                          Vg + (size_t)(t + 1) * BK * DH, tid);
        }
        __syncthreads();
        uint32_t* tmp = bufA; bufA = bufB; bufB = tmp;
    }

    // ---- epilogue: reduce l over the quad, scale, store ----
    float* Og = O + ((size_t)bh * SEQ + q0) * DH;
    #pragma unroll
    for (int rb = 0; rb < 2; ++rb) {
        float l0 = ls[rb][0], l1 = ls[rb][1];
        l0 += __shfl_xor_sync(0xffffffffu, l0, 1);
        l0 += __shfl_xor_sync(0xffffffffu, l0, 2);
        l1 += __shfl_xor_sync(0xffffffffu, l1, 1);
        l1 += __shfl_xor_sync(0xffffffffu, l1, 2);
        const float i0 = 1.f / l0, i1 = 1.f / l1;
        #pragma unroll
        for (int nt = 0; nt < 8; ++nt) {
            *(float2*)(Og + rr[rb][0] * DH + nt * 8 + 2 * c) =
                make_float2(oc[rb][nt][0] * i0, oc[rb][nt][1] * i0);
            *(float2*)(Og + rr[rb][1] * DH + nt * 8 + 2 * c) =
                make_float2(oc[rb][nt][2] * i1, oc[rb][nt][3] * i1);
        }
    }
}

extern "C" void kernel_launch(void* const* d_in, const int* in_sizes, int n_in,
                              void* d_out, int out_size) {
    const float* Q = (const float*)d_in[0];
    const float* K = (const float*)d_in[1];
    const float* V = (const float*)d_in[2];
    const int*   M = (const int*)d_in[3];
    float* O = (float*)d_out;
    (void)in_sizes; (void)n_in; (void)out_size;

    cudaFuncSetAttribute(fa_mma_kernel,
                         cudaFuncAttributeMaxDynamicSharedMemorySize,
                         (int)SMEM_BYTES);
    dim3 grid(SEQ / BQ, 32);   // 16 q-tiles x (B*H)
    fa_mma_kernel<<<grid, NTHR, SMEM_BYTES>>>(Q, K, V, M, O);
}

// round 8
// speedup vs baseline: 1.1705x; 1.0689x over previous
#include <cuda_runtime.h>
#include <cstdint>

#define DINL __device__ __forceinline__

namespace {
constexpr int SEQ = 2048, DH = 64, BQ = 128, BK = 64, NTILE = SEQ / BK;
constexpr int NTHR = 128;                  // 4 warps x 32 q-rows each
// smem: 4 parts (KH,KL,VH,VL), each 64 rows x 32 words (8 KB)
constexpr int KHW = 0, KLW = 2048, VHW = 4096, VLW = 6144;
constexpr int BUFW = 8192;                 // words per tile buffer (32 KB)
constexpr uint32_t BUF_BYTES = BUFW * 4u;  // 32768
constexpr uint32_t SMEM_BYTES = 2u * BUF_BYTES;   // 65536 (double buffered)
}  // namespace

DINL uint32_t pkbf(float lo, float hi) {   // word = {lo16: bf(lo), hi16: bf(hi)}
    uint32_t r;
    asm("cvt.rn.bf16x2.f32 %0, %1, %2;" : "=r"(r) : "f"(hi), "f"(lo));
    return r;
}
DINL float lof(uint32_t w) { return __uint_as_float(w << 16); }
DINL float hif(uint32_t w) { return __uint_as_float(w & 0xffff0000u); }

DINL void split_store(uint32_t* hp, uint32_t* lp, float x, float y) {
    uint32_t h = pkbf(x, y);
    *hp = h;
    *lp = pkbf(x - lof(h), y - hif(h));
}

DINL void mma16816(float* cc, const uint32_t* a, uint32_t b0, uint32_t b1) {
    asm volatile(
        "mma.sync.aligned.m16n8k16.row.col.f32.bf16.bf16.f32 "
        "{%0,%1,%2,%3}, {%4,%5,%6,%7}, {%8,%9}, {%0,%1,%2,%3};"
        : "+f"(cc[0]), "+f"(cc[1]), "+f"(cc[2]), "+f"(cc[3])
        : "r"(a[0]), "r"(a[1]), "r"(a[2]), "r"(a[3]), "r"(b0), "r"(b1));
}

DINL void ldsm4(uint32_t* r, uint32_t addr) {
    asm volatile(
        "ldmatrix.sync.aligned.m8n8.x4.shared.b16 {%0,%1,%2,%3}, [%4];"
        : "=r"(r[0]), "=r"(r[1]), "=r"(r[2]), "=r"(r[3]) : "r"(addr));
}

DINL uint32_t smem_u32(const void* p) {
    uint32_t a;
    asm("{ .reg .u64 t; cvta.to.shared.u64 t, %1; cvt.u32.u64 %0, t; }"
        : "=r"(a) : "l"(p));
    return a;
}

// Convert one K/V tile (64 keys x 64 d fp32) into hi/lo bf16 smem parts.
// K stored [key][d] (rows=key); V^T stored [d][key] (rows=d).
// Row = 64 bf16 = 8 chunks of 16B; chunk index XOR-swizzled by (row&7).
DINL void fill_tile(uint32_t* buf, const float* Kt, const float* Vt, int tid) {
    {
        const int row = tid >> 1, col0 = (tid & 1) * 32;
        const float4* kp = (const float4*)(Kt + row * DH + col0);
        uint32_t hw[16], lw[16];
        #pragma unroll
        for (int j = 0; j < 8; ++j) {
            float4 v = kp[j];
            split_store(&hw[2 * j], &lw[2 * j], v.x, v.y);
            split_store(&hw[2 * j + 1], &lw[2 * j + 1], v.z, v.w);
        }
        const uint32_t ro = (uint32_t)(row * 32);
        #pragma unroll
        for (int jc = 0; jc < 4; ++jc) {
            int cs = ((col0 >> 3) + jc) ^ (row & 7);
            *(uint4*)(buf + KHW + ro + cs * 4) =
                make_uint4(hw[jc*4], hw[jc*4+1], hw[jc*4+2], hw[jc*4+3]);
            *(uint4*)(buf + KLW + ro + cs * 4) =
                make_uint4(lw[jc*4], lw[jc*4+1], lw[jc*4+2], lw[jc*4+3]);
        }
    }
    {
        const int d = tid >> 1, kh = tid & 1;
        uint32_t hw[16], lw[16];
        #pragma unroll
        for (int j = 0; j < 16; ++j) {
            float a = Vt[(kh * 32 + 2 * j) * DH + d];
            float b = Vt[(kh * 32 + 2 * j + 1) * DH + d];
            split_store(&hw[j], &lw[j], a, b);
        }
        const uint32_t ro = (uint32_t)(d * 32);
        #pragma unroll
        for (int jc = 0; jc < 4; ++jc) {
            int cs = (kh * 4 + jc) ^ (d & 7);
            *(uint4*)(buf + VHW + ro + cs * 4) =
                make_uint4(hw[jc*4], hw[jc*4+1], hw[jc*4+2], hw[jc*4+3]);
            *(uint4*)(buf + VLW + ro + cs * 4) =
                make_uint4(lw[jc*4], lw[jc*4+1], lw[jc*4+2], lw[jc*4+3]);
        }
    }
}

__global__ void __launch_bounds__(NTHR, 2)
fa_mma_kernel(const float* __restrict__ Q, const float* __restrict__ K,
              const float* __restrict__ V, const int* __restrict__ M,
              float* __restrict__ O) {
    extern __shared__ uint32_t sm[];
    const uint32_t smb = smem_u32(sm);
    const int tid = threadIdx.x;
    const int w = tid >> 5, lane = tid & 31;
    const int g = lane >> 2, c = lane & 3;
    const int rl = lane & 7;               // ldmatrix row-within-matrix
    const int kb = (lane >> 4) & 1;        // matrix pair select (m>>1)
    const int kc = (lane >> 3) & 1;        // chunk select (m&1)
    const int q0 = blockIdx.x * BQ, bh = blockIdx.y;

    const float* Qg = Q + ((size_t)bh * SEQ + q0) * DH;
    const float* Kg = K + (size_t)bh * SEQ * DH;
    const float* Vg = V + (size_t)bh * SEQ * DH;

    int rr[2][2];
    rr[0][0] = w * 32 + g;      rr[0][1] = rr[0][0] + 8;
    rr[1][0] = rr[0][0] + 16;   rr[1][1] = rr[1][0] + 8;
    const int* Mbase = M + ((size_t)bh * SEQ + q0) * SEQ;

    // thread-specific ldmatrix base: block(kb)*1024 + row(rl)*128 bytes
    const uint32_t thrb = smb + (uint32_t)(kb * 1024 + rl * 128);

    // ---- Q fragments (x 1/8 exact), hi/lo bf16, persistent ----
    uint32_t qh[2][4][4], ql[2][4][4];
    #pragma unroll
    for (int rb = 0; rb < 2; ++rb) {
        #pragma unroll
        for (int s = 0; s < 4; ++s) {
            const int col = 16 * s + 2 * c;
            float2 x0 = *(const float2*)(Qg + rr[rb][0] * DH + col);
            float2 x1 = *(const float2*)(Qg + rr[rb][1] * DH + col);
            float2 x2 = *(const float2*)(Qg + rr[rb][0] * DH + col + 8);
            float2 x3 = *(const float2*)(Qg + rr[rb][1] * DH + col + 8);
            split_store(&qh[rb][s][0], &ql[rb][s][0], x0.x * .125f, x0.y * .125f);
            split_store(&qh[rb][s][1], &ql[rb][s][1], x1.x * .125f, x1.y * .125f);
            split_store(&qh[rb][s][2], &ql[rb][s][2], x2.x * .125f, x2.y * .125f);
            split_store(&qh[rb][s][3], &ql[rb][s][3], x3.x * .125f, x3.y * .125f);
        }
    }

    fill_tile(sm, Kg, Vg, tid);
    __syncthreads();

    float oc[2][8][4] = {};
    float ls[2][2] = {};
    uint32_t bufsel = 0;

    for (int t = 0; t < NTILE; ++t) {
        #pragma unroll
        for (int hf = 0; hf < 2; ++hf) {
            // ---- mask bits for this half (LDG early; drains under QK) ----
            uint32_t mbits[2];
            #pragma unroll
            for (int rb = 0; rb < 2; ++rb) {
                const int* M0 =
                    Mbase + (size_t)rr[rb][0] * SEQ + t * BK + hf * 32 + 2 * c;
                const int* M1 =
                    Mbase + (size_t)rr[rb][1] * SEQ + t * BK + hf * 32 + 2 * c;
                uint32_t bits = 0;
                #pragma unroll
                for (int j = 0; j < 4; ++j) {
                    int2 m0 = *(const int2*)(M0 + j * 8);
                    int2 m1 = *(const int2*)(M1 + j * 8);
                    bits |= ((m0.x ? 1u : 0u) | (m0.y ? 2u : 0u) |
                             (m1.x ? 4u : 0u) | (m1.y ? 8u : 0u)) << (j * 4);
                }
                mbits[rb] = bits;
            }

            // ---- S(half) = Qhat K^T : per s, 4 LDSM.x4 then 24 MMAs ----
            float sc[2][4][4] = {};
            #pragma unroll
            for (int s = 0; s < 4; ++s) {
                uint32_t bw[8], lw[8];
                const uint32_t ct = (uint32_t)(((2 * s + kc) ^ rl) << 4);
                const uint32_t ab =
                    thrb + bufsel + ct + (uint32_t)(hf * 4 * 1024);
                ldsm4(bw,     ab);                 // KH, nt0..1
                ldsm4(bw + 4, ab + 2048);          // KH, nt2..3
                ldsm4(lw,     ab + 8192);          // KL, nt0..1
                ldsm4(lw + 4, ab + 8192 + 2048);   // KL, nt2..3
                #pragma unroll
                for (int j = 0; j < 4; ++j) {
                    mma16816(sc[0][j], qh[0][s], bw[2 * j], bw[2 * j + 1]);
                    mma16816(sc[1][j], qh[1][s], bw[2 * j], bw[2 * j + 1]);
                }
                #pragma unroll
                for (int j = 0; j < 4; ++j) {
                    mma16816(sc[0][j], qh[0][s], lw[2 * j], lw[2 * j + 1]);
                    mma16816(sc[1][j], qh[1][s], lw[2 * j], lw[2 * j + 1]);
                }
                #pragma unroll
                for (int j = 0; j < 4; ++j) {
                    mma16816(sc[0][j], ql[0][s], bw[2 * j], bw[2 * j + 1]);
                    mma16816(sc[1][j], ql[1][s], bw[2 * j], bw[2 * j + 1]);
                }
            }

            // ---- softmax in place: p = mask ? exp(s) : 0 (unshifted) ----
            #pragma unroll
            for (int rb = 0; rb < 2; ++rb) {
                #pragma unroll
                for (int j = 0; j < 4; ++j) {
                    const uint32_t b = mbits[rb] >> (j * 4);
                    float e0 = (b & 1u) ? __expf(sc[rb][j][0]) : 0.f;
                    float e1 = (b & 2u) ? __expf(sc[rb][j][1]) : 0.f;
                    float e2 = (b & 4u) ? __expf(sc[rb][j][2]) : 0.f;
                    float e3 = (b & 8u) ? __expf(sc[rb][j][3]) : 0.f;
                    ls[rb][0] += e0 + e1;
                    ls[rb][1] += e2 + e3;
                    sc[rb][j][0] = e0; sc[rb][j][1] = e1;
                    sc[rb][j][2] = e2; sc[rb][j][3] = e3;
                }
            }

            // ---- O += P(half) V : per sp, 2 groups of [4 LDSM + 24 MMA] ----
            #pragma unroll
            for (int sp = 0; sp < 2; ++sp) {
                const int s = hf * 2 + sp;       // key chunk for V^T k-dim
                uint32_t pah[2][4], pal[2][4];
                #pragma unroll
                for (int rb = 0; rb < 2; ++rb) {
                    split_store(&pah[rb][0], &pal[rb][0],
                                sc[rb][2 * sp][0], sc[rb][2 * sp][1]);
                    split_store(&pah[rb][1], &pal[rb][1],
                                sc[rb][2 * sp][2], sc[rb][2 * sp][3]);
                    split_store(&pah[rb][2], &pal[rb][2],
                                sc[rb][2 * sp + 1][0], sc[rb][2 * sp + 1][1]);
                    split_store(&pah[rb][3], &pal[rb][3],
                                sc[rb][2 * sp + 1][2], sc[rb][2 * sp + 1][3]);
                }
                #pragma unroll
                for (int pg = 0; pg < 2; ++pg) {   // d-blocks 0-3 / 4-7
                    uint32_t vw[8], vl[8];
                    const uint32_t ct = (uint32_t)(((2 * s + kc) ^ rl) << 4);
                    const uint32_t ab = thrb + bufsel + ct + 16384u +
                                        (uint32_t)(pg * 4 * 1024);
                    ldsm4(vw,     ab);                 // VH, d-blk 2pg..+1
                    ldsm4(vw + 4, ab + 2048);          // VH, d-blk +2..+3
                    ldsm4(vl,     ab + 8192);          // VL
                    ldsm4(vl + 4, ab + 8192 + 2048);
                    #pragma unroll
                    for (int j = 0; j < 4; ++j) {
                        mma16816(oc[0][pg * 4 + j], pah[0], vw[2*j], vw[2*j+1]);
                        mma16816(oc[1][pg * 4 + j], pah[1], vw[2*j], vw[2*j+1]);
                    }
                    #pragma unroll
                    for (int j = 0; j < 4; ++j) {
                        mma16816(oc[0][pg * 4 + j], pah[0], vl[2*j], vl[2*j+1]);
                        mma16816(oc[1][pg * 4 + j], pah[1], vl[2*j], vl[2*j+1]);
                    }
                    #pragma unroll
                    for (int j = 0; j < 4; ++j) {
                        mma16816(oc[0][pg * 4 + j], pal[0], vw[2*j], vw[2*j+1]);
                        mma16816(oc[1][pg * 4 + j], pal[1], vw[2*j], vw[2*j+1]);
                    }
                }
            }

            // prefetch+convert next tile between halves (sc is dead here)
            if (hf == 0 && t + 1 < NTILE)
                fill_tile(sm + ((bufsel ^ BUF_BYTES) >> 2),
                          Kg + (size_t)(t + 1) * BK * DH,
                          Vg + (size_t)(t + 1) * BK * DH, tid);
        }
        __syncthreads();
        bufsel ^= BUF_BYTES;
    }

    // ---- epilogue: reduce l over the quad, scale, store ----
    float* Og = O + ((size_t)bh * SEQ + q0) * DH;
    #pragma unroll
    for (int rb = 0; rb < 2; ++rb) {
        float l0 = ls[rb][0], l1 = ls[rb][1];
        l0 += __shfl_xor_sync(0xffffffffu, l0, 1);
        l0 += __shfl_xor_sync(0xffffffffu, l0, 2);
        l1 += __shfl_xor_sync(0xffffffffu, l1, 1);
        l1 += __shfl_xor_sync(0xffffffffu, l1, 2);
        const float i0 = 1.f / l0, i1 = 1.f / l1;
        #pragma unroll
        for (int nt = 0; nt < 8; ++nt) {
            *(float2*)(Og + rr[rb][0] * DH + nt * 8 + 2 * c) =
                make_float2(oc[rb][nt][0] * i0, oc[rb][nt][1] * i0);
            *(float2*)(Og + rr[rb][1] * DH + nt * 8 + 2 * c) =
                make_float2(oc[rb][nt][2] * i1, oc[rb][nt][3] * i1);
        }
    }
}

extern "C" void kernel_launch(void* const* d_in, const int* in_sizes, int n_in,
                              void* d_out, int out_size) {
    const float* Q = (const float*)d_in[0];
    const float* K = (const float*)d_in[1];
    const float* V = (const float*)d_in[2];
    const int*   M = (const int*)d_in[3];
    float* O = (float*)d_out;
    (void)in_sizes; (void)n_in; (void)out_size;

    cudaFuncSetAttribute(fa_mma_kernel,
                         cudaFuncAttributeMaxDynamicSharedMemorySize,
                         (int)SMEM_BYTES);
    dim3 grid(SEQ / BQ, 32);   // 16 q-tiles x (B*H)
    fa_mma_kernel<<<grid, NTHR, SMEM_BYTES>>>(Q, K, V, M, O);
}

// round 9
// speedup vs baseline: 1.3045x; 1.1145x over previous
#include <cuda_runtime.h>
#include <cstdint>

#define DINL __device__ __forceinline__

namespace {
constexpr int SEQ = 2048, DH = 64, BQ = 128, BK = 64, NTILE = SEQ / BK;
constexpr int NTHR = 128;                  // 4 warps x 32 q-rows each
constexpr int NBH = 32;                    // B*H
// tile image: 4 parts (KH,KL,VH,VL), each 64 rows x 32 words (8 KB)
constexpr int KHW = 0, KLW = 2048, VHW = 4096, VLW = 6144;
constexpr int TILE_U4 = 2048;              // uint4 per tile image (32 KB)
constexpr uint32_t BUF_BYTES = 32768;
constexpr uint32_t SMEM_BYTES = 2u * BUF_BYTES;   // 64 KB double buffered
}  // namespace

// Pre-split, pre-swizzled K/V tile images (bf16 hi/lo), 33.5 MB scratch.
__device__ uint4 gKV[(size_t)NBH * NTILE * TILE_U4];

DINL uint32_t pkbf(float lo, float hi) {   // word = {lo16: bf(lo), hi16: bf(hi)}
    uint32_t r;
    asm("cvt.rn.bf16x2.f32 %0, %1, %2;" : "=r"(r) : "f"(hi), "f"(lo));
    return r;
}
DINL float lof(uint32_t w) { return __uint_as_float(w << 16); }
DINL float hif(uint32_t w) { return __uint_as_float(w & 0xffff0000u); }

DINL void split_store(uint32_t* hp, uint32_t* lp, float x, float y) {
    uint32_t h = pkbf(x, y);
    *hp = h;
    *lp = pkbf(x - lof(h), y - hif(h));
}

DINL void mma16816(float* cc, const uint32_t* a, uint32_t b0, uint32_t b1) {
    asm volatile(
        "mma.sync.aligned.m16n8k16.row.col.f32.bf16.bf16.f32 "
        "{%0,%1,%2,%3}, {%4,%5,%6,%7}, {%8,%9}, {%0,%1,%2,%3};"
        : "+f"(cc[0]), "+f"(cc[1]), "+f"(cc[2]), "+f"(cc[3])
        : "r"(a[0]), "r"(a[1]), "r"(a[2]), "r"(a[3]), "r"(b0), "r"(b1));
}

DINL void ldsm4(uint32_t* r, uint32_t addr) {
    asm volatile(
        "ldmatrix.sync.aligned.m8n8.x4.shared.b16 {%0,%1,%2,%3}, [%4];"
        : "=r"(r[0]), "=r"(r[1]), "=r"(r[2]), "=r"(r[3]) : "r"(addr));
}

DINL uint32_t smem_u32(const void* p) {
    uint32_t a;
    asm("{ .reg .u64 t; cvta.to.shared.u64 t, %1; cvt.u32.u64 %0, t; }"
        : "=r"(a) : "l"(p));
    return a;
}

DINL void cpa16(uint32_t dst, const void* src) {
    asm volatile("cp.async.cg.shared.global [%0], [%1], 16;"
                 :: "r"(dst), "l"(src) : "memory");
}
DINL void cpa_commit() { asm volatile("cp.async.commit_group;" ::: "memory"); }
DINL void cpa_wait_all() { asm volatile("cp.async.wait_group 0;" ::: "memory"); }

// ---------------- prep kernel: build split/swizzled tile images ------------
// K stored [key][d] (rows=key); V^T stored [d][key] (rows=d).
// Row = 64 bf16 = 8 chunks of 16B; chunk index XOR-swizzled by (row&7).
__global__ void __launch_bounds__(NTHR)
prep_kv(const float* __restrict__ K, const float* __restrict__ V) {
    const int t = blockIdx.x, bh = blockIdx.y, tid = threadIdx.x;
    const float* Kt = K + ((size_t)bh * SEQ + (size_t)t * BK) * DH;
    const float* Vt = V + ((size_t)bh * SEQ + (size_t)t * BK) * DH;
    uint32_t* buf = (uint32_t*)(gKV + ((size_t)bh * NTILE + t) * TILE_U4);
    {
        const int row = tid >> 1, col0 = (tid & 1) * 32;
        const float4* kp = (const float4*)(Kt + row * DH + col0);
        uint32_t hw[16], lw[16];
        #pragma unroll
        for (int j = 0; j < 8; ++j) {
            float4 v = kp[j];
            split_store(&hw[2 * j], &lw[2 * j], v.x, v.y);
            split_store(&hw[2 * j + 1], &lw[2 * j + 1], v.z, v.w);
        }
        const uint32_t ro = (uint32_t)(row * 32);
        #pragma unroll
        for (int jc = 0; jc < 4; ++jc) {
            int cs = ((col0 >> 3) + jc) ^ (row & 7);
            *(uint4*)(buf + KHW + ro + cs * 4) =
                make_uint4(hw[jc*4], hw[jc*4+1], hw[jc*4+2], hw[jc*4+3]);
            *(uint4*)(buf + KLW + ro + cs * 4) =
                make_uint4(lw[jc*4], lw[jc*4+1], lw[jc*4+2], lw[jc*4+3]);
        }
    }
    {
        const int d = tid >> 1, kh = tid & 1;
        uint32_t hw[16], lw[16];
        #pragma unroll
        for (int j = 0; j < 16; ++j) {
            float a = Vt[(kh * 32 + 2 * j) * DH + d];
            float b = Vt[(kh * 32 + 2 * j + 1) * DH + d];
            split_store(&hw[j], &lw[j], a, b);
        }
        const uint32_t ro = (uint32_t)(d * 32);
        #pragma unroll
        for (int jc = 0; jc < 4; ++jc) {
            int cs = (kh * 4 + jc) ^ (d & 7);
            *(uint4*)(buf + VHW + ro + cs * 4) =
                make_uint4(hw[jc*4], hw[jc*4+1], hw[jc*4+2], hw[jc*4+3]);
            *(uint4*)(buf + VLW + ro + cs * 4) =
                make_uint4(lw[jc*4], lw[jc*4+1], lw[jc*4+2], lw[jc*4+3]);
        }
    }
}

// ---------------- main kernel ----------------------------------------------
__global__ void __launch_bounds__(NTHR, 2)
fa_mma_kernel(const float* __restrict__ Q, const int* __restrict__ M,
              float* __restrict__ O) {
    extern __shared__ uint32_t sm[];
    const uint32_t smb = smem_u32(sm);
    const int tid = threadIdx.x;
    const int w = tid >> 5, lane = tid & 31;
    const int g = lane >> 2, c = lane & 3;
    const int rl = lane & 7;               // ldmatrix row-within-matrix
    const int kb = (lane >> 4) & 1;        // matrix pair select
    const int kc = (lane >> 3) & 1;        // chunk select
    const int q0 = blockIdx.x * BQ, bh = blockIdx.y;

    const float* Qg = Q + ((size_t)bh * SEQ + q0) * DH;
    const uint4* KVg = gKV + (size_t)bh * NTILE * TILE_U4;

    int rr[2][2];
    rr[0][0] = w * 32 + g;      rr[0][1] = rr[0][0] + 8;
    rr[1][0] = rr[0][0] + 16;   rr[1][1] = rr[1][0] + 8;
    const int* Mbase = M + ((size_t)bh * SEQ + q0) * SEQ;

    // thread-constant ldmatrix base + per-s column offsets
    const uint32_t thrb = smb + (uint32_t)(kb * 1024 + rl * 128);
    uint32_t ctc[4];
    #pragma unroll
    for (int s = 0; s < 4; ++s) ctc[s] = (uint32_t)(((2 * s + kc) ^ rl) << 4);

    // ---- Q fragments (x 1/8 exact), hi/lo bf16, persistent ----
    uint32_t qh[2][4][4], ql[2][4][4];
    #pragma unroll
    for (int rb = 0; rb < 2; ++rb) {
        #pragma unroll
        for (int s = 0; s < 4; ++s) {
            const int col = 16 * s + 2 * c;
            float2 x0 = *(const float2*)(Qg + rr[rb][0] * DH + col);
            float2 x1 = *(const float2*)(Qg + rr[rb][1] * DH + col);
            float2 x2 = *(const float2*)(Qg + rr[rb][0] * DH + col + 8);
            float2 x3 = *(const float2*)(Qg + rr[rb][1] * DH + col + 8);
            split_store(&qh[rb][s][0], &ql[rb][s][0], x0.x * .125f, x0.y * .125f);
            split_store(&qh[rb][s][1], &ql[rb][s][1], x1.x * .125f, x1.y * .125f);
            split_store(&qh[rb][s][2], &ql[rb][s][2], x2.x * .125f, x2.y * .125f);
            split_store(&qh[rb][s][3], &ql[rb][s][3], x3.x * .125f, x3.y * .125f);
        }
    }

    // prime: async-copy tile 0
    #pragma unroll
    for (int j = 0; j < 16; ++j)
        cpa16(smb + (uint32_t)((tid + j * 128) * 16), KVg + tid + j * 128);
    cpa_commit();
    cpa_wait_all();
    __syncthreads();

    float oc[2][8][4] = {};
    float ls[2][2] = {};
    uint32_t bufsel = 0;

    for (int t = 0; t < NTILE; ++t) {
        // issue next tile's async copy first; it drains under this tile's MMAs
        if (t + 1 < NTILE) {
            const uint4* src = KVg + (size_t)(t + 1) * TILE_U4;
            const uint32_t dst = smb + (bufsel ^ BUF_BYTES);
            #pragma unroll
            for (int j = 0; j < 16; ++j)
                cpa16(dst + (uint32_t)((tid + j * 128) * 16), src + tid + j * 128);
            cpa_commit();
        }

        #pragma unroll
        for (int hf = 0; hf < 2; ++hf) {
            // ---- mask bits for this half (LDG early; drains under QK) ----
            uint32_t mbits[2];
            #pragma unroll
            for (int rb = 0; rb < 2; ++rb) {
                const int* M0 =
                    Mbase + (size_t)rr[rb][0] * SEQ + t * BK + hf * 32 + 2 * c;
                const int* M1 =
                    Mbase + (size_t)rr[rb][1] * SEQ + t * BK + hf * 32 + 2 * c;
                uint32_t bits = 0;
                #pragma unroll
                for (int j = 0; j < 4; ++j) {
                    int2 m0 = *(const int2*)(M0 + j * 8);
                    int2 m1 = *(const int2*)(M1 + j * 8);
                    bits |= ((m0.x ? 1u : 0u) | (m0.y ? 2u : 0u) |
                             (m1.x ? 4u : 0u) | (m1.y ? 8u : 0u)) << (j * 4);
                }
                mbits[rb] = bits;
            }

            // ---- S(half) = Qhat K^T : per s, 4 LDSM.x4 then 24 MMAs ----
            float sc[2][4][4] = {};
            #pragma unroll
            for (int s = 0; s < 4; ++s) {
                uint32_t bw[8], lw[8];
                const uint32_t ab =
                    thrb + bufsel + ctc[s] + (uint32_t)(hf * 4096);
                ldsm4(bw,     ab);                 // KH, nt0..1
                ldsm4(bw + 4, ab + 2048);          // KH, nt2..3
                ldsm4(lw,     ab + 8192);          // KL, nt0..1
                ldsm4(lw + 4, ab + 8192 + 2048);   // KL, nt2..3
                #pragma unroll
                for (int j = 0; j < 4; ++j) {
                    mma16816(sc[0][j], qh[0][s], bw[2 * j], bw[2 * j + 1]);
                    mma16816(sc[1][j], qh[1][s], bw[2 * j], bw[2 * j + 1]);
                }
                #pragma unroll
                for (int j = 0; j < 4; ++j) {
                    mma16816(sc[0][j], qh[0][s], lw[2 * j], lw[2 * j + 1]);
                    mma16816(sc[1][j], qh[1][s], lw[2 * j], lw[2 * j + 1]);
                }
                #pragma unroll
                for (int j = 0; j < 4; ++j) {
                    mma16816(sc[0][j], ql[0][s], bw[2 * j], bw[2 * j + 1]);
                    mma16816(sc[1][j], ql[1][s], bw[2 * j], bw[2 * j + 1]);
                }
            }

            // ---- softmax in place: p = mask ? exp(s) : 0 (unshifted) ----
            #pragma unroll
            for (int rb = 0; rb < 2; ++rb) {
                #pragma unroll
                for (int j = 0; j < 4; ++j) {
                    const uint32_t b = mbits[rb] >> (j * 4);
                    float e0 = (b & 1u) ? __expf(sc[rb][j][0]) : 0.f;
                    float e1 = (b & 2u) ? __expf(sc[rb][j][1]) : 0.f;
                    float e2 = (b & 4u) ? __expf(sc[rb][j][2]) : 0.f;
                    float e3 = (b & 8u) ? __expf(sc[rb][j][3]) : 0.f;
                    ls[rb][0] += e0 + e1;
                    ls[rb][1] += e2 + e3;
                    sc[rb][j][0] = e0; sc[rb][j][1] = e1;
                    sc[rb][j][2] = e2; sc[rb][j][3] = e3;
                }
            }

            // ---- O += P(half) V : per sp, 2 groups of [4 LDSM + 24 MMA] ----
            #pragma unroll
            for (int sp = 0; sp < 2; ++sp) {
                const int s = hf * 2 + sp;       // key chunk for V^T k-dim
                uint32_t pah[2][4], pal[2][4];
                #pragma unroll
                for (int rb = 0; rb < 2; ++rb) {
                    split_store(&pah[rb][0], &pal[rb][0],
                                sc[rb][2 * sp][0], sc[rb][2 * sp][1]);
                    split_store(&pah[rb][1], &pal[rb][1],
                                sc[rb][2 * sp][2], sc[rb][2 * sp][3]);
                    split_store(&pah[rb][2], &pal[rb][2],
                                sc[rb][2 * sp + 1][0], sc[rb][2 * sp + 1][1]);
                    split_store(&pah[rb][3], &pal[rb][3],
                                sc[rb][2 * sp + 1][2], sc[rb][2 * sp + 1][3]);
                }
                #pragma unroll
                for (int pg = 0; pg < 2; ++pg) {   // d-blocks 0-3 / 4-7
                    uint32_t vw[8], vl[8];
                    const uint32_t ab = thrb + bufsel + ctc[s] + 16384u +
                                        (uint32_t)(pg * 4096);
                    ldsm4(vw,     ab);                 // VH
                    ldsm4(vw + 4, ab + 2048);
                    ldsm4(vl,     ab + 8192);          // VL
                    ldsm4(vl + 4, ab + 8192 + 2048);
                    #pragma unroll
                    for (int j = 0; j < 4; ++j) {
                        mma16816(oc[0][pg * 4 + j], pah[0], vw[2*j], vw[2*j+1]);
                        mma16816(oc[1][pg * 4 + j], pah[1], vw[2*j], vw[2*j+1]);
                    }
                    #pragma unroll
                    for (int j = 0; j < 4; ++j) {
                        mma16816(oc[0][pg * 4 + j], pah[0], vl[2*j], vl[2*j+1]);
                        mma16816(oc[1][pg * 4 + j], pah[1], vl[2*j], vl[2*j+1]);
                    }
                    #pragma unroll
                    for (int j = 0; j < 4; ++j) {
                        mma16816(oc[0][pg * 4 + j], pal[0], vw[2*j], vw[2*j+1]);
                        mma16816(oc[1][pg * 4 + j], pal[1], vw[2*j], vw[2*j+1]);
                    }
                }
            }
        }
        cpa_wait_all();
        __syncthreads();
        bufsel ^= BUF_BYTES;
    }

    // ---- epilogue: reduce l over the quad, scale, store ----
    float* Og = O + ((size_t)bh * SEQ + q0) * DH;
    #pragma unroll
    for (int rb = 0; rb < 2; ++rb) {
        float l0 = ls[rb][0], l1 = ls[rb][1];
        l0 += __shfl_xor_sync(0xffffffffu, l0, 1);
        l0 += __shfl_xor_sync(0xffffffffu, l0, 2);
        l1 += __shfl_xor_sync(0xffffffffu, l1, 1);
        l1 += __shfl_xor_sync(0xffffffffu, l1, 2);
        const float i0 = 1.f / l0, i1 = 1.f / l1;
        #pragma unroll
        for (int nt = 0; nt < 8; ++nt) {
            *(float2*)(Og + rr[rb][0] * DH + nt * 8 + 2 * c) =
                make_float2(oc[rb][nt][0] * i0, oc[rb][nt][1] * i0);
            *(float2*)(Og + rr[rb][1] * DH + nt * 8 + 2 * c) =
                make_float2(oc[rb][nt][2] * i1, oc[rb][nt][3] * i1);
        }
    }
}

extern "C" void kernel_launch(void* const* d_in, const int* in_sizes, int n_in,
                              void* d_out, int out_size) {
    const float* Q = (const float*)d_in[0];
    const float* K = (const float*)d_in[1];
    const float* V = (const float*)d_in[2];
    const int*   M = (const int*)d_in[3];
    float* O = (float*)d_out;
    (void)in_sizes; (void)n_in; (void)out_size;

    prep_kv<<<dim3(NTILE, NBH), NTHR>>>(K, V);

    cudaFuncSetAttribute(fa_mma_kernel,
                         cudaFuncAttributeMaxDynamicSharedMemorySize,
                         (int)SMEM_BYTES);
    dim3 grid(SEQ / BQ, NBH);   // 16 q-tiles x (B*H)
    fa_mma_kernel<<<grid, NTHR, SMEM_BYTES>>>(Q, M, O);
}

// round 10
// speedup vs baseline: 1.3640x; 1.0456x over previous
#include <cuda_runtime.h>
#include <cstdint>

#define DINL __device__ __forceinline__

namespace {
constexpr int SEQ = 2048, DH = 64, BQ = 128, BK = 64, NTILE = SEQ / BK;
constexpr int NTHR = 128, NBH = 32;
constexpr int TILE_U4 = 2048;              // 32 KB KV tile image
// smem byte offsets: QH | QL | KV double buffer
constexpr uint32_t QL_B = 16384, KV_B = 32768, BUF_BYTES = 32768;
constexpr uint32_t SMEM_BYTES = KV_B + 2u * BUF_BYTES;   // 98304
// inside a KV buffer (bytes): KH 0, KL 8192, VH 16384, VL 24576
}  // namespace

__device__ uint4 gKV[(size_t)NBH * NTILE * TILE_U4];

DINL uint32_t pkbf(float lo, float hi) {
    uint32_t r;
    asm("cvt.rn.bf16x2.f32 %0, %1, %2;" : "=r"(r) : "f"(hi), "f"(lo));
    return r;
}
DINL float lof(uint32_t w) { return __uint_as_float(w << 16); }
DINL float hif(uint32_t w) { return __uint_as_float(w & 0xffff0000u); }
DINL void split_store(uint32_t* hp, uint32_t* lp, float x, float y) {
    uint32_t h = pkbf(x, y);
    *hp = h;
    *lp = pkbf(x - lof(h), y - hif(h));
}
DINL void mma16816(float* cc, const uint32_t* a, uint32_t b0, uint32_t b1) {
    asm volatile(
        "mma.sync.aligned.m16n8k16.row.col.f32.bf16.bf16.f32 "
        "{%0,%1,%2,%3}, {%4,%5,%6,%7}, {%8,%9}, {%0,%1,%2,%3};"
        : "+f"(cc[0]), "+f"(cc[1]), "+f"(cc[2]), "+f"(cc[3])
        : "r"(a[0]), "r"(a[1]), "r"(a[2]), "r"(a[3]), "r"(b0), "r"(b1));
}
DINL void ldsm4(uint32_t* r, uint32_t addr) {
    asm volatile(
        "ldmatrix.sync.aligned.m8n8.x4.shared.b16 {%0,%1,%2,%3}, [%4];"
        : "=r"(r[0]), "=r"(r[1]), "=r"(r[2]), "=r"(r[3]) : "r"(addr));
}
DINL uint32_t smem_u32(const void* p) {
    uint32_t a;
    asm("{ .reg .u64 t; cvta.to.shared.u64 t, %1; cvt.u32.u64 %0, t; }"
        : "=r"(a) : "l"(p));
    return a;
}
DINL void cpa16(uint32_t dst, const void* src) {
    asm volatile("cp.async.cg.shared.global [%0], [%1], 16;"
                 :: "r"(dst), "l"(src) : "memory");
}
DINL void cpa_commit() { asm volatile("cp.async.commit_group;" ::: "memory"); }
DINL void cpa_wait_all() { asm volatile("cp.async.wait_group 0;" ::: "memory"); }

// ---------------- prep kernel: split/swizzled K,V^T tile images -------------
__global__ void __launch_bounds__(NTHR)
prep_kv(const float* __restrict__ K, const float* __restrict__ V) {
    const int t = blockIdx.x, bh = blockIdx.y, tid = threadIdx.x;
    const float* Kt = K + ((size_t)bh * SEQ + (size_t)t * BK) * DH;
    const float* Vt = V + ((size_t)bh * SEQ + (size_t)t * BK) * DH;
    uint32_t* buf = (uint32_t*)(gKV + ((size_t)bh * NTILE + t) * TILE_U4);
    {
        const int row = tid >> 1, col0 = (tid & 1) * 32;
        const float4* kp = (const float4*)(Kt + row * DH + col0);
        uint32_t hw[16], lw[16];
        #pragma unroll
        for (int j = 0; j < 8; ++j) {
            float4 v = kp[j];
            split_store(&hw[2 * j], &lw[2 * j], v.x, v.y);
            split_store(&hw[2 * j + 1], &lw[2 * j + 1], v.z, v.w);
        }
        const uint32_t ro = (uint32_t)(row * 32);
        #pragma unroll
        for (int jc = 0; jc < 4; ++jc) {
            int cs = ((col0 >> 3) + jc) ^ (row & 7);
            *(uint4*)(buf + ro + cs * 4) =
                make_uint4(hw[jc*4], hw[jc*4+1], hw[jc*4+2], hw[jc*4+3]);
            *(uint4*)(buf + 2048 + ro + cs * 4) =
                make_uint4(lw[jc*4], lw[jc*4+1], lw[jc*4+2], lw[jc*4+3]);
        }
    }
    {
        const int d = tid >> 1, kh = tid & 1;
        uint32_t hw[16], lw[16];
        #pragma unroll
        for (int j = 0; j < 16; ++j) {
            float a = Vt[(kh * 32 + 2 * j) * DH + d];
            float b = Vt[(kh * 32 + 2 * j + 1) * DH + d];
            split_store(&hw[j], &lw[j], a, b);
        }
        const uint32_t ro = (uint32_t)(d * 32);
        #pragma unroll
        for (int jc = 0; jc < 4; ++jc) {
            int cs = (kh * 4 + jc) ^ (d & 7);
            *(uint4*)(buf + 4096 + ro + cs * 4) =
                make_uint4(hw[jc*4], hw[jc*4+1], hw[jc*4+2], hw[jc*4+3]);
            *(uint4*)(buf + 6144 + ro + cs * 4) =
                make_uint4(lw[jc*4], lw[jc*4+1], lw[jc*4+2], lw[jc*4+3]);
        }
    }
}

// ---------------- main kernel ------------------------------------------------

// QK for one 32-key half HF into SC (zeroed by caller).
#define QK_HALF(SC, HF)                                                        \
    {                                                                          \
        _Pragma("unroll")                                                      \
        for (int s = 0; s < 4; ++s) {                                          \
            uint32_t qa0[4], qa1[4], qx0[4], qx1[4], bw[8], lw[8];             \
            ldsm4(qa0, qb0 + qoff0[s]);                                        \
            ldsm4(qa1, qb1 + qoff1[s]);                                        \
            ldsm4(qx0, qb0 + qoff0[s] + QL_B);                                 \
            ldsm4(qx1, qb1 + qoff1[s] + QL_B);                                 \
            const uint32_t ab = kvb + ctc[s] + (uint32_t)((HF) * 4096);        \
            ldsm4(bw, ab);                                                     \
            ldsm4(bw + 4, ab + 2048);                                          \
            ldsm4(lw, ab + 8192);                                              \
            ldsm4(lw + 4, ab + 10240);                                         \
            _Pragma("unroll")                                                  \
            for (int j = 0; j < 4; ++j) {                                      \
                mma16816(SC[0][j], qa0, bw[2 * j], bw[2 * j + 1]);             \
                mma16816(SC[1][j], qa1, bw[2 * j], bw[2 * j + 1]);             \
            }                                                                  \
            _Pragma("unroll")                                                  \
            for (int j = 0; j < 4; ++j) {                                      \
                mma16816(SC[0][j], qa0, lw[2 * j], lw[2 * j + 1]);             \
                mma16816(SC[1][j], qa1, lw[2 * j], lw[2 * j + 1]);             \
            }                                                                  \
            _Pragma("unroll")                                                  \
            for (int j = 0; j < 4; ++j) {                                      \
                mma16816(SC[0][j], qx0, bw[2 * j], bw[2 * j + 1]);             \
                mma16816(SC[1][j], qx1, bw[2 * j], bw[2 * j + 1]);             \
            }                                                                  \
        }                                                                      \
    }

#define LOAD_MB(MB, HF)                                                        \
    {                                                                          \
        _Pragma("unroll")                                                      \
        for (int rb = 0; rb < 2; ++rb) {                                       \
            const int* M0 = Mb + (size_t)(w * 32 + rb * 16 + g) * SEQ +        \
                            t * BK + (HF) * 32 + 2 * c;                        \
            const int* M1 = M0 + 8 * SEQ;                                      \
            uint32_t bits = 0;                                                 \
            _Pragma("unroll")                                                  \
            for (int j = 0; j < 4; ++j) {                                      \
                int2 m0 = *(const int2*)(M0 + j * 8);                          \
                int2 m1 = *(const int2*)(M1 + j * 8);                          \
                bits |= ((m0.x ? 1u : 0u) | (m0.y ? 2u : 0u) |                 \
                         (m1.x ? 4u : 0u) | (m1.y ? 8u : 0u)) << (j * 4);      \
            }                                                                  \
            MB[rb] = bits;                                                     \
        }                                                                      \
    }

#define EXP_HALF(SC, MB)                                                       \
    {                                                                          \
        _Pragma("unroll")                                                      \
        for (int rb = 0; rb < 2; ++rb) {                                       \
            _Pragma("unroll")                                                  \
            for (int j = 0; j < 4; ++j) {                                      \
                const uint32_t b = MB[rb] >> (j * 4);                          \
                float e0 = (b & 1u) ? __expf(SC[rb][j][0]) : 0.f;              \
                float e1 = (b & 2u) ? __expf(SC[rb][j][1]) : 0.f;              \
                float e2 = (b & 4u) ? __expf(SC[rb][j][2]) : 0.f;              \
                float e3 = (b & 8u) ? __expf(SC[rb][j][3]) : 0.f;              \
                ls[rb][0] += e0 + e1;                                          \
                ls[rb][1] += e2 + e3;                                          \
                SC[rb][j][0] = e0; SC[rb][j][1] = e1;                          \
                SC[rb][j][2] = e2; SC[rb][j][3] = e3;                          \
            }                                                                  \
        }                                                                      \
    }

#define PV_HALF(SC, HF)                                                        \
    {                                                                          \
        _Pragma("unroll")                                                      \
        for (int sp = 0; sp < 2; ++sp) {                                       \
            const int s = (HF) * 2 + sp;                                       \
            uint32_t pah[2][4], pal[2][4];                                     \
            _Pragma("unroll")                                                  \
            for (int rb = 0; rb < 2; ++rb) {                                   \
                split_store(&pah[rb][0], &pal[rb][0],                          \
                            SC[rb][2 * sp][0], SC[rb][2 * sp][1]);             \
                split_store(&pah[rb][1], &pal[rb][1],                          \
                            SC[rb][2 * sp][2], SC[rb][2 * sp][3]);             \
                split_store(&pah[rb][2], &pal[rb][2],                          \
                            SC[rb][2 * sp + 1][0], SC[rb][2 * sp + 1][1]);     \
                split_store(&pah[rb][3], &pal[rb][3],                          \
                            SC[rb][2 * sp + 1][2], SC[rb][2 * sp + 1][3]);     \
            }                                                                  \
            _Pragma("unroll")                                                  \
            for (int pg = 0; pg < 2; ++pg) {                                   \
                uint32_t vw[8], vl[8];                                         \
                const uint32_t ab =                                            \
                    kvb + ctc[s] + 16384u + (uint32_t)(pg * 4096);             \
                ldsm4(vw, ab);                                                 \
                ldsm4(vw + 4, ab + 2048);                                      \
                ldsm4(vl, ab + 8192);                                          \
                ldsm4(vl + 4, ab + 10240);                                     \
                _Pragma("unroll")                                              \
                for (int j = 0; j < 4; ++j) {                                  \
                    mma16816(oc[0][pg * 4 + j], pah[0], vw[2*j], vw[2*j+1]);   \
                    mma16816(oc[1][pg * 4 + j], pah[1], vw[2*j], vw[2*j+1]);   \
                }                                                              \
                _Pragma("unroll")                                              \
                for (int j = 0; j < 4; ++j) {                                  \
                    mma16816(oc[0][pg * 4 + j], pah[0], vl[2*j], vl[2*j+1]);   \
                    mma16816(oc[1][pg * 4 + j], pah[1], vl[2*j], vl[2*j+1]);   \
                }                                                              \
                _Pragma("unroll")                                              \
                for (int j = 0; j < 4; ++j) {                                  \
                    mma16816(oc[0][pg * 4 + j], pal[0], vw[2*j], vw[2*j+1]);   \
                    mma16816(oc[1][pg * 4 + j], pal[1], vw[2*j], vw[2*j+1]);   \
                }                                                              \
            }                                                                  \
        }                                                                      \
    }

__global__ void __launch_bounds__(NTHR, 2)
fa_mma_kernel(const float* __restrict__ Q, const int* __restrict__ M,
              float* __restrict__ O) {
    extern __shared__ uint32_t sm[];
    const uint32_t smb = smem_u32(sm);
    const int tid = threadIdx.x;
    const int w = tid >> 5, lane = tid & 31;
    const int g = lane >> 2, c = lane & 3;
    const int rl = lane & 7, kb = (lane >> 4) & 1, kc = (lane >> 3) & 1;
    const int qr = lane & 15, qc2 = lane >> 4;
    const int q0 = blockIdx.x * BQ, bh = blockIdx.y;

    const uint4* KVg = gKV + (size_t)bh * NTILE * TILE_U4;
    const int* Mb = M + ((size_t)bh * SEQ + q0) * SEQ;

    // prime: async-copy KV tile 0 while we build the Q smem image
    #pragma unroll
    for (int j = 0; j < 16; ++j)
        cpa16(smb + KV_B + (uint32_t)((tid + j * 128) * 16), KVg + tid + j * 128);
    cpa_commit();

    // ---- Q image: row=tid, x0.125, hi/lo bf16, XOR-swizzled chunks ----
    {
        const float4* qp =
            (const float4*)(Q + ((size_t)bh * SEQ + q0 + tid) * DH);
        uint32_t hw[32], lw[32];
        #pragma unroll
        for (int j = 0; j < 16; ++j) {
            float4 v = qp[j];
            split_store(&hw[2 * j], &lw[2 * j], v.x * .125f, v.y * .125f);
            split_store(&hw[2 * j + 1], &lw[2 * j + 1], v.z * .125f, v.w * .125f);
        }
        const uint32_t ro = (uint32_t)(tid * 32);
        uint32_t* buf = sm;
        #pragma unroll
        for (int jc = 0; jc < 8; ++jc) {
            int cs = jc ^ (tid & 7);
            *(uint4*)(buf + ro + cs * 4) =
                make_uint4(hw[jc*4], hw[jc*4+1], hw[jc*4+2], hw[jc*4+3]);
            *(uint4*)(buf + 4096 + ro + cs * 4) =
                make_uint4(lw[jc*4], lw[jc*4+1], lw[jc*4+2], lw[jc*4+3]);
        }
    }
    cpa_wait_all();
    __syncthreads();

    // thread-constant ldmatrix addressing
    uint32_t qb0, qb1, qoff0[4], qoff1[4], ctc[4];
    {
        const int r0 = w * 32 + qr, r1 = r0 + 16;
        qb0 = smb + (uint32_t)(r0 * 128);
        qb1 = smb + (uint32_t)(r1 * 128);
        #pragma unroll
        for (int s = 0; s < 4; ++s) {
            qoff0[s] = (uint32_t)((((2 * s + qc2) ^ (r0 & 7)) << 4));
            qoff1[s] = (uint32_t)((((2 * s + qc2) ^ (r1 & 7)) << 4));
            ctc[s] = (uint32_t)((((2 * s + kc) ^ rl) << 4));
        }
    }
    const uint32_t kvthr = smb + KV_B + (uint32_t)(kb * 1024 + rl * 128);

    float oc[2][8][4] = {};
    float ls[2][2] = {};
    uint32_t bufsel = 0;

    for (int t = 0; t < NTILE; ++t) {
        if (t + 1 < NTILE) {
            const uint4* src = KVg + (size_t)(t + 1) * TILE_U4;
            const uint32_t dst = smb + KV_B + (bufsel ^ BUF_BYTES);
            #pragma unroll
            for (int j = 0; j < 16; ++j)
                cpa16(dst + (uint32_t)((tid + j * 128) * 16), src + tid + j * 128);
            cpa_commit();
        }
        const uint32_t kvb = kvthr + bufsel;

        float scA[2][4][4] = {};
        QK_HALF(scA, 0)
        uint32_t mb0[2];
        LOAD_MB(mb0, 0)
        EXP_HALF(scA, mb0)

        float scB[2][4][4] = {};
        QK_HALF(scB, 1)          // independent MMAs queue behind exp users
        uint32_t mb1[2];
        LOAD_MB(mb1, 1)
        PV_HALF(scA, 0)          // fills tensor pipe while QK(h1) drains
        EXP_HALF(scB, mb1)
        PV_HALF(scB, 1)

        cpa_wait_all();
        __syncthreads();
        bufsel ^= BUF_BYTES;
    }

    // ---- epilogue ----
    float* Og = O + ((size_t)bh * SEQ + q0) * DH;
    #pragma unroll
    for (int rb = 0; rb < 2; ++rb) {
        float l0 = ls[rb][0], l1 = ls[rb][1];
        l0 += __shfl_xor_sync(0xffffffffu, l0, 1);
        l0 += __shfl_xor_sync(0xffffffffu, l0, 2);
        l1 += __shfl_xor_sync(0xffffffffu, l1, 1);
        l1 += __shfl_xor_sync(0xffffffffu, l1, 2);
        const float i0 = 1.f / l0, i1 = 1.f / l1;
        const int r0 = w * 32 + rb * 16 + g;
        #pragma unroll
        for (int nt = 0; nt < 8; ++nt) {
            *(float2*)(Og + r0 * DH + nt * 8 + 2 * c) =
                make_float2(oc[rb][nt][0] * i0, oc[rb][nt][1] * i0);
            *(float2*)(Og + (r0 + 8) * DH + nt * 8 + 2 * c) =
                make_float2(oc[rb][nt][2] * i1, oc[rb][nt][3] * i1);
        }
    }
}

extern "C" void kernel_launch(void* const* d_in, const int* in_sizes, int n_in,
                              void* d_out, int out_size) {
    const float* Q = (const float*)d_in[0];
    const float* K = (const float*)d_in[1];
    const float* V = (const float*)d_in[2];
    const int*   M = (const int*)d_in[3];
    float* O = (float*)d_out;
    (void)in_sizes; (void)n_in; (void)out_size;

    prep_kv<<<dim3(NTILE, NBH), NTHR>>>(K, V);

    cudaFuncSetAttribute(fa_mma_kernel,
                         cudaFuncAttributeMaxDynamicSharedMemorySize,
                         (int)SMEM_BYTES);
    dim3 grid(SEQ / BQ, NBH);
    fa_mma_kernel<<<grid, NTHR, SMEM_BYTES>>>(Q, M, O);
}